// round 11
// baseline (speedup 1.0000x reference)
#include <cuda_runtime.h>
#include <cuda_bf16.h>
#include <math.h>
#include <stdint.h>

#define N_NODES 20000
#define N_EDGES 160000
#define D 128
#define H 4
#define HD 512
#define N_LAYERS 3
#define KK 256            // split storage: 128 hi | 128 lo

// ---------------- scratch (device globals) ------------
__device__ float g_xl[(size_t)N_NODES * HD];
__device__ float g_xr[(size_t)N_NODES * HD];
__device__ __nv_bfloat16 g_hh[(size_t)N_NODES * KK];      // split activations [hi|lo]
__device__ __nv_bfloat16 g_wlr[(size_t)1024 * KK];        // split [Wl|Wr]^T [n][hi|lo]
__device__ __nv_bfloat16 g_wf[(size_t)128 * KK];          // split Wf^T
__device__ float g_blr[1024];
__device__ int   g_cnt[N_NODES];
__device__ float g_easum[N_NODES * 2];
__device__ int   g_offs[N_NODES + 1];
__device__ int   g_cursor[N_NODES];
__device__ int   g_csr[N_EDGES];

__device__ __forceinline__ uint32_t smem_u32(const void* p) {
    uint32_t a;
    asm("{ .reg .u64 t; cvta.to.shared.u64 t, %1; cvt.u32.u64 %0, t; }" : "=r"(a) : "l"(p));
    return a;
}
__device__ __forceinline__ void split_bf16(float v, __nv_bfloat16& hi, __nv_bfloat16& lo) {
    hi = __float2bfloat16(v);
    lo = __float2bfloat16(v - __bfloat162float(hi));
}

// ---------------- CSR build ----------------
__global__ void init_kernel() {
    int i = blockIdx.x * blockDim.x + threadIdx.x;
    if (i < N_NODES) { g_cnt[i] = 0; g_easum[2*i] = 0.f; g_easum[2*i+1] = 0.f; }
}
__global__ void count_kernel(const int* __restrict__ dst, const float* __restrict__ eattr) {
    int e = blockIdx.x * blockDim.x + threadIdx.x;
    if (e < N_EDGES) {
        int d = dst[e];
        atomicAdd(&g_cnt[d], 1);
        atomicAdd(&g_easum[2*d],   eattr[2*e]);
        atomicAdd(&g_easum[2*d+1], eattr[2*e+1]);
    }
}
// warp-shuffle hierarchical scan (3 syncthreads per 1024-chunk)
__global__ void scan_kernel() {
    __shared__ int wsum[32];
    __shared__ int base_s;
    int tid = threadIdx.x, lane = tid & 31, wd = tid >> 5;
    if (tid == 0) base_s = 0;
    __syncthreads();
    for (int start = 0; start < N_NODES; start += 1024) {
        int i = start + tid;
        int v = (i < N_NODES) ? g_cnt[i] : 0;
        int s = v;
        #pragma unroll
        for (int off = 1; off < 32; off <<= 1) {
            int t = __shfl_up_sync(0xffffffffu, s, off);
            if (lane >= off) s += t;
        }
        if (lane == 31) wsum[wd] = s;
        __syncthreads();
        if (wd == 0) {
            int ws = wsum[lane];
            #pragma unroll
            for (int off = 1; off < 32; off <<= 1) {
                int t = __shfl_up_sync(0xffffffffu, ws, off);
                if (lane >= off) ws += t;
            }
            wsum[lane] = ws;
        }
        __syncthreads();
        int wpre = (wd > 0) ? wsum[wd - 1] : 0;
        int incl = s + wpre;
        int base = base_s;
        if (i < N_NODES) {
            g_offs[i] = base + incl - v;
            g_cursor[i] = base + incl - v;
        }
        __syncthreads();
        if (tid == 1023) base_s = base + incl;
        __syncthreads();
    }
    if (tid == 0) g_offs[N_NODES] = N_EDGES;
}
__global__ void fill_kernel(const int* __restrict__ dst) {
    int e = blockIdx.x * blockDim.x + threadIdx.x;
    if (e < N_EDGES) g_csr[atomicAdd(&g_cursor[dst[e]], 1)] = e;
}

// ---------------- prep: all weights (merged) + input split ----------------
__global__ void prep_w_kernel(const float* __restrict__ Wl, const float* __restrict__ Wr,
                              const float* __restrict__ bl, const float* __restrict__ br,
                              const float* __restrict__ Wf) {
    int i = blockIdx.x * blockDim.x + threadIdx.x;
    if (i < 1024 * 128) {
        int n = i >> 7, k = i & 127;
        float v = (n < 512) ? Wl[k * 512 + n] : Wr[k * 512 + (n - 512)];
        __nv_bfloat16 hi, lo;
        split_bf16(v, hi, lo);
        g_wlr[(size_t)n * KK + k] = hi;
        g_wlr[(size_t)n * KK + 128 + k] = lo;
        if (k == 0) g_blr[n] = (n < 512) ? bl[n] : br[n - 512];
    } else if (i < 1024 * 128 + 128 * 128) {
        int j = i - 1024 * 128;
        int n = j >> 7, k = j & 127;
        __nv_bfloat16 hi, lo;
        split_bf16(Wf[k * 128 + n], hi, lo);
        g_wf[(size_t)n * KK + k] = hi;
        g_wf[(size_t)n * KK + 128 + k] = lo;
    }
}
__global__ void split_act_kernel(const float* __restrict__ src) {
    int i = blockIdx.x * blockDim.x + threadIdx.x;
    if (i < N_NODES * 128) {
        int r = i >> 7, c = i & 127;
        __nv_bfloat16 hi, lo;
        split_bf16(src[i], hi, lo);
        g_hh[(size_t)r * KK + c] = hi;
        g_hh[(size_t)r * KK + 128 + c] = lo;
    }
}

// ---------------- bf16 mma.sync GEMM, phased-A, 3 CTAs/SM (round-9, unchanged) ----------------
#define A_LDKB 272
#define A_HALF_BYTES (128 * A_LDKB)
#define B_LDKB 528
#define B_BYTES (64 * B_LDKB)
#define GEMM_SMEM (A_HALF_BYTES + B_BYTES)   // 68608 -> 3 CTAs/SM

__device__ __forceinline__ void ldsm4(uint32_t* r, uint32_t addr) {
    asm volatile("ldmatrix.sync.aligned.m8n8.x4.shared.b16 {%0,%1,%2,%3}, [%4];"
                 : "=r"(r[0]), "=r"(r[1]), "=r"(r[2]), "=r"(r[3]) : "r"(addr));
}
__device__ __forceinline__ void mma16816(float* c, const uint32_t* a, const uint32_t* b) {
    asm volatile(
        "mma.sync.aligned.m16n8k16.row.col.f32.bf16.bf16.f32 "
        "{%0,%1,%2,%3}, {%4,%5,%6,%7}, {%8,%9}, {%0,%1,%2,%3};"
        : "+f"(c[0]), "+f"(c[1]), "+f"(c[2]), "+f"(c[3])
        : "r"(a[0]), "r"(a[1]), "r"(a[2]), "r"(a[3]), "r"(b[0]), "r"(b[1]));
}
__device__ __forceinline__ void loadA(char* smem, int tid, int m0, int kbase, int M) {
    #pragma unroll
    for (int c = tid; c < 2048; c += 256) {
        int r = c >> 4;
        int kc = (c & 15) * 8;
        int gm = m0 + r;
        uint4 v = make_uint4(0, 0, 0, 0);
        if (gm < M) v = *(const uint4*)&g_hh[(size_t)gm * KK + kbase + kc];
        *(uint4*)(smem + r * A_LDKB + kc * 2) = v;
    }
}

template <int DSTSEL>
__global__ void __launch_bounds__(256, 3)
mma_gemm(const float* __restrict__ bias_param, int M) {
    extern __shared__ char smem[];
    uint32_t usb = smem_u32(smem);
    int tid = threadIdx.x, wid = tid >> 5, lane = tid & 31;
    int m0 = blockIdx.y * 128;
    int n0 = blockIdx.x * 64;

    const __nv_bfloat16* Bw = (DSTSEL == 0) ? g_wf : g_wlr;
    const float* bias = (DSTSEL == 0) ? bias_param : g_blr;

    loadA(smem, tid, m0, 0, M);
    #pragma unroll
    for (int c = tid; c < 2048; c += 256) {
        int r = c >> 5;
        int kc = (c & 31) * 8;
        uint4 v = *(const uint4*)&Bw[(size_t)(n0 + r) * KK + kc];
        *(uint4*)(smem + A_HALF_BYTES + r * B_LDKB + kc * 2) = v;
    }
    __syncthreads();

    int wm = wid & 3;
    int wn = wid >> 2;

    uint32_t aoff = usb + (uint32_t)((wm * 32 + (lane & 15)) * A_LDKB + ((lane >> 4) * 8) * 2);
    uint32_t boff = usb + A_HALF_BYTES +
        (uint32_t)((wn * 32 + ((lane >> 4) << 3) + (lane & 7)) * B_LDKB + (((lane >> 3) & 1) * 8) * 2);

    float acc[2][4][4];
    #pragma unroll
    for (int i = 0; i < 2; i++)
        #pragma unroll
        for (int j = 0; j < 4; j++)
            #pragma unroll
            for (int q = 0; q < 4; q++) acc[i][j][q] = 0.f;

    // phase 1: Ahi x Bhi + Ahi x Blo
    #pragma unroll
    for (int k8 = 0; k8 < 8; k8++) {
        int ak = k8 * 16;
        uint32_t ra[2][4];
        ldsm4(ra[0], aoff + ak * 2);
        ldsm4(ra[1], aoff + ak * 2 + 16 * A_LDKB);

        uint32_t rbh[2][4], rbl[2][4];
        #pragma unroll
        for (int g = 0; g < 2; g++) {
            ldsm4(rbh[g], boff + ak * 2 + g * 16 * B_LDKB);
            ldsm4(rbl[g], boff + (128 + ak) * 2 + g * 16 * B_LDKB);
        }
        #pragma unroll
        for (int mi = 0; mi < 2; mi++)
            #pragma unroll
            for (int g = 0; g < 2; g++) {
                mma16816(acc[mi][2 * g],     ra[mi], &rbh[g][0]);
                mma16816(acc[mi][2 * g + 1], ra[mi], &rbh[g][2]);
                mma16816(acc[mi][2 * g],     ra[mi], &rbl[g][0]);
                mma16816(acc[mi][2 * g + 1], ra[mi], &rbl[g][2]);
            }
    }

    __syncthreads();
    loadA(smem, tid, m0, 128, M);
    __syncthreads();

    // phase 2: Alo x Bhi
    #pragma unroll
    for (int k8 = 0; k8 < 8; k8++) {
        int ak = k8 * 16;
        uint32_t ra[2][4];
        ldsm4(ra[0], aoff + ak * 2);
        ldsm4(ra[1], aoff + ak * 2 + 16 * A_LDKB);

        uint32_t rbh[2][4];
        #pragma unroll
        for (int g = 0; g < 2; g++)
            ldsm4(rbh[g], boff + ak * 2 + g * 16 * B_LDKB);

        #pragma unroll
        for (int mi = 0; mi < 2; mi++)
            #pragma unroll
            for (int g = 0; g < 2; g++) {
                mma16816(acc[mi][2 * g],     ra[mi], &rbh[g][0]);
                mma16816(acc[mi][2 * g + 1], ra[mi], &rbh[g][2]);
            }
    }

    int lr = lane >> 2;
    int lc = (lane & 3) * 2;
    #pragma unroll
    for (int mi = 0; mi < 2; mi++) {
        #pragma unroll
        for (int ni = 0; ni < 4; ni++) {
            int gn = n0 + wn * 32 + ni * 8 + lc;
            float bx = bias[gn], by = bias[gn + 1];
            #pragma unroll
            for (int half = 0; half < 2; half++) {
                int gm = m0 + wm * 32 + mi * 16 + lr + half * 8;
                if (gm < M) {
                    float vx = acc[mi][ni][2 * half] + bx;
                    float vy = acc[mi][ni][2 * half + 1] + by;
                    if (DSTSEL == 0) {
                        __nv_bfloat16 hx, lx, hy, ly;
                        split_bf16(vx, hx, lx);
                        split_bf16(vy, hy, ly);
                        __nv_bfloat162 hh2; hh2.x = hx; hh2.y = hy;
                        __nv_bfloat162 ll2; ll2.x = lx; ll2.y = ly;
                        *(__nv_bfloat162*)&g_hh[(size_t)gm * KK + gn] = hh2;
                        *(__nv_bfloat162*)&g_hh[(size_t)gm * KK + 128 + gn] = ll2;
                    } else {
                        float2 v = make_float2(vx, vy);
                        if (gn < 512) *(float2*)&g_xl[(size_t)gm * 512 + gn] = v;
                        else          *(float2*)&g_xr[(size_t)gm * 512 + (gn - 512)] = v;
                    }
                }
            }
        }
    }
}

// ---------------- fused GATv2 edge/aggregate kernel (2-way ILP online softmax) ----------------
#define ECH 64
template <int LAST>
__global__ void __launch_bounds__(128)
edge_kernel(const int* __restrict__ esrc,
            const float* __restrict__ eattr,
            const float* __restrict__ We,
            const float* __restrict__ att,
            const float* __restrict__ bias_out,
            float* __restrict__ hout) {
    int n = blockIdx.x;
    int h = threadIdx.x >> 5;
    int l = threadIdx.x & 31;

    __shared__ float comb[H][D];
    __shared__ int   s_src[ECH];
    __shared__ float s_ea0[ECH];
    __shared__ float s_ea1[ECH];

    int basec = h * D + 4 * l;
    float4 xr4 = *(const float4*)&g_xr[(size_t)n * HD + basec];
    float4 at4 = *(const float4*)&att[basec];
    float4 we0 = *(const float4*)&We[basec];
    float4 we1 = *(const float4*)&We[HD + basec];

    // two independent online-softmax chains (even/odd edges)
    float4 accA = make_float4(0.f, 0.f, 0.f, 0.f);
    float4 accB = make_float4(0.f, 0.f, 0.f, 0.f);
    float mA = -INFINITY, dA = 0.f;
    float mB = -INFINITY, dB = 0.f;

    int rs = g_offs[n], re = g_offs[n + 1];
    int total = re - rs + 1;                 // +1 virtual self-loop (last)
    float inv = 1.0f / fmaxf((float)(re - rs), 1.0f);

    for (int base = 0; base < total; base += ECH) {
        int cnt = min(ECH, total - base);
        if (threadIdx.x < cnt) {
            int gi = rs + base + threadIdx.x;
            if (gi < re) {
                int e = g_csr[gi];
                s_src[threadIdx.x] = esrc[e];
                s_ea0[threadIdx.x] = eattr[2 * e];
                s_ea1[threadIdx.x] = eattr[2 * e + 1];
            } else {                         // self-loop (mean edge_attr)
                s_src[threadIdx.x] = n;
                s_ea0[threadIdx.x] = g_easum[2 * n] * inv;
                s_ea1[threadIdx.x] = g_easum[2 * n + 1] * inv;
            }
        }
        __syncthreads();

        float4 xA, xB;
        xA = *(const float4*)&g_xl[(size_t)s_src[0] * HD + basec];
        if (cnt > 1) xB = *(const float4*)&g_xl[(size_t)s_src[1] * HD + basec];

        for (int j = 0; j < cnt; j += 2) {
            float4 nxA, nxB;
            if (j + 2 < cnt) nxA = *(const float4*)&g_xl[(size_t)s_src[j + 2] * HD + basec];
            if (j + 3 < cnt) nxB = *(const float4*)&g_xl[(size_t)s_src[j + 3] * HD + basec];

            // ---- chain A: edge j ----
            {
                float ea0 = s_ea0[j], ea1 = s_ea1[j];
                float t0 = xA.x + xr4.x + ea0 * we0.x + ea1 * we1.x;
                float t1 = xA.y + xr4.y + ea0 * we0.y + ea1 * we1.y;
                float t2 = xA.z + xr4.z + ea0 * we0.z + ea1 * we1.z;
                float t3 = xA.w + xr4.w + ea0 * we0.w + ea1 * we1.w;
                t0 = (t0 > 0.f) ? t0 : 0.2f * t0;
                t1 = (t1 > 0.f) ? t1 : 0.2f * t1;
                t2 = (t2 > 0.f) ? t2 : 0.2f * t2;
                t3 = (t3 > 0.f) ? t3 : 0.2f * t3;
                float p = t0 * at4.x + t1 * at4.y + t2 * at4.z + t3 * at4.w;
                #pragma unroll
                for (int off = 16; off > 0; off >>= 1)
                    p += __shfl_xor_sync(0xffffffffu, p, off);
                float nm = fmaxf(mA, p);
                float r = __expf(mA - nm);
                float w = __expf(p - nm);
                accA.x = accA.x * r + w * xA.x;
                accA.y = accA.y * r + w * xA.y;
                accA.z = accA.z * r + w * xA.z;
                accA.w = accA.w * r + w * xA.w;
                dA = dA * r + w;
                mA = nm;
            }
            // ---- chain B: edge j+1 ----
            if (j + 1 < cnt) {
                float ea0 = s_ea0[j + 1], ea1 = s_ea1[j + 1];
                float t0 = xB.x + xr4.x + ea0 * we0.x + ea1 * we1.x;
                float t1 = xB.y + xr4.y + ea0 * we0.y + ea1 * we1.y;
                float t2 = xB.z + xr4.z + ea0 * we0.z + ea1 * we1.z;
                float t3 = xB.w + xr4.w + ea0 * we0.w + ea1 * we1.w;
                t0 = (t0 > 0.f) ? t0 : 0.2f * t0;
                t1 = (t1 > 0.f) ? t1 : 0.2f * t1;
                t2 = (t2 > 0.f) ? t2 : 0.2f * t2;
                t3 = (t3 > 0.f) ? t3 : 0.2f * t3;
                float p = t0 * at4.x + t1 * at4.y + t2 * at4.z + t3 * at4.w;
                #pragma unroll
                for (int off = 16; off > 0; off >>= 1)
                    p += __shfl_xor_sync(0xffffffffu, p, off);
                float nm = fmaxf(mB, p);
                float r = __expf(mB - nm);
                float w = __expf(p - nm);
                accB.x = accB.x * r + w * xB.x;
                accB.y = accB.y * r + w * xB.y;
                accB.z = accB.z * r + w * xB.z;
                accB.w = accB.w * r + w * xB.w;
                dB = dB * r + w;
                mB = nm;
            }
            xA = nxA;
            xB = nxB;
        }
        __syncthreads();     // protect smem stage before next chunk overwrites
    }

    // ---- merge chains (chain A always non-empty: total >= 1) ----
    float nm = fmaxf(mA, mB);
    float rA = __expf(mA - nm);
    float rB = __expf(mB - nm);          // 0 if chain B empty (mB = -inf)
    float denom = dA * rA + dB * rB;
    float4 acc;
    acc.x = accA.x * rA + accB.x * rB;
    acc.y = accA.y * rA + accB.y * rB;
    acc.z = accA.z * rA + accB.z * rB;
    acc.w = accA.w * rA + accB.w * rB;

    float invd = 1.0f / denom;
    comb[h][4 * l + 0] = acc.x * invd;
    comb[h][4 * l + 1] = acc.y * invd;
    comb[h][4 * l + 2] = acc.z * invd;
    comb[h][4 * l + 3] = acc.w * invd;
    __syncthreads();

    int d = threadIdx.x;
    float v = 0.25f * (comb[0][d] + comb[1][d] + comb[2][d] + comb[3][d]) + bias_out[d];
    v = (v > 0.f) ? v : 0.01f * v;
    if (LAST) {
        hout[(size_t)n * D + d] = v;
    } else {
        __nv_bfloat16 hi, lo;
        split_bf16(v, hi, lo);
        g_hh[(size_t)n * KK + d] = hi;
        g_hh[(size_t)n * KK + 128 + d] = lo;
    }
}

// ---------------- launch ----------------
extern "C" void kernel_launch(void* const* d_in, const int* in_sizes, int n_in,
                              void* d_out, int out_size) {
    const float* x        = (const float*)d_in[0];
    const int* eidx       = (const int*)d_in[1];
    const float* eattr    = (const float*)d_in[2];
    const float* Wf       = (const float*)d_in[3];
    const float* bf       = (const float*)d_in[4];
    const float* Wl       = (const float*)d_in[5];
    const float* bl       = (const float*)d_in[6];
    const float* Wr       = (const float*)d_in[7];
    const float* br       = (const float*)d_in[8];
    const float* We       = (const float*)d_in[9];
    const float* att      = (const float*)d_in[10];
    const float* bias_out = (const float*)d_in[11];
    float* h              = (float*)d_out;

    const int* esrc = eidx;
    const int* edst = eidx + N_EDGES;

    cudaFuncSetAttribute(mma_gemm<0>, cudaFuncAttributeMaxDynamicSharedMemorySize, GEMM_SMEM);
    cudaFuncSetAttribute(mma_gemm<3>, cudaFuncAttributeMaxDynamicSharedMemorySize, GEMM_SMEM);

    const int MTILES = (N_NODES + 127) / 128;   // 157

    prep_w_kernel<<<(1024 * 128 + 128 * 128 + 255) / 256, 256>>>(Wl, Wr, bl, br, Wf);
    split_act_kernel<<<(N_NODES * 128 + 255) / 256, 256>>>(x);

    mma_gemm<0><<<dim3(2, MTILES), 256, GEMM_SMEM>>>(bf, N_NODES);
    mma_gemm<3><<<dim3(16, MTILES), 256, GEMM_SMEM>>>(nullptr, N_NODES);

    init_kernel<<<(N_NODES + 255) / 256, 256>>>();
    count_kernel<<<(N_EDGES + 255) / 256, 256>>>(edst, eattr);
    scan_kernel<<<1, 1024>>>();
    fill_kernel<<<(N_EDGES + 255) / 256, 256>>>(edst);

    for (int layer = 0; layer < N_LAYERS; ++layer) {
        if (layer > 0)
            mma_gemm<3><<<dim3(16, MTILES), 256, GEMM_SMEM>>>(nullptr, N_NODES);
        if (layer < N_LAYERS - 1)
            edge_kernel<0><<<N_NODES, 128>>>(esrc, eattr, We, att, bias_out, h);
        else
            edge_kernel<1><<<N_NODES, 128>>>(esrc, eattr, We, att, bias_out, h);
    }
}

// round 12
// speedup vs baseline: 1.1232x; 1.1232x over previous
#include <cuda_runtime.h>
#include <cuda_bf16.h>
#include <math.h>
#include <stdint.h>

#define N_NODES 20000
#define N_EDGES 160000
#define D 128
#define H 4
#define HD 512
#define N_LAYERS 3
#define KK 256            // split storage: 128 hi | 128 lo

// ---------------- scratch (device globals) ------------
__device__ float g_xl[(size_t)N_NODES * HD];
__device__ float g_xr[(size_t)N_NODES * HD];
__device__ __nv_bfloat16 g_hh[(size_t)N_NODES * KK];      // split activations [hi|lo]
__device__ __nv_bfloat16 g_wlr[(size_t)1024 * KK];        // split [Wl|Wr]^T [n][hi|lo]
__device__ __nv_bfloat16 g_wf[(size_t)128 * KK];          // split Wf^T
__device__ float g_blr[1024];
__device__ int   g_cnt[N_NODES];
__device__ float g_easum[N_NODES * 2];
__device__ int   g_offs[N_NODES + 1];
__device__ int   g_cursor[N_NODES];
__device__ int   g_csr[N_EDGES];

__device__ __forceinline__ uint32_t smem_u32(const void* p) {
    uint32_t a;
    asm("{ .reg .u64 t; cvta.to.shared.u64 t, %1; cvt.u32.u64 %0, t; }" : "=r"(a) : "l"(p));
    return a;
}
__device__ __forceinline__ void split_bf16(float v, __nv_bfloat16& hi, __nv_bfloat16& lo) {
    hi = __float2bfloat16(v);
    lo = __float2bfloat16(v - __bfloat162float(hi));
}

// ---------------- CSR build ----------------
__global__ void init_kernel() {
    int i = blockIdx.x * blockDim.x + threadIdx.x;
    if (i < N_NODES) { g_cnt[i] = 0; g_easum[2*i] = 0.f; g_easum[2*i+1] = 0.f; }
}
__global__ void count_kernel(const int* __restrict__ dst, const float* __restrict__ eattr) {
    int e = blockIdx.x * blockDim.x + threadIdx.x;
    if (e < N_EDGES) {
        int d = dst[e];
        atomicAdd(&g_cnt[d], 1);
        atomicAdd(&g_easum[2*d],   eattr[2*e]);
        atomicAdd(&g_easum[2*d+1], eattr[2*e+1]);
    }
}
// warp-shuffle hierarchical scan (3 syncthreads per 1024-chunk)
__global__ void scan_kernel() {
    __shared__ int wsum[32];
    __shared__ int base_s;
    int tid = threadIdx.x, lane = tid & 31, wd = tid >> 5;
    if (tid == 0) base_s = 0;
    __syncthreads();
    for (int start = 0; start < N_NODES; start += 1024) {
        int i = start + tid;
        int v = (i < N_NODES) ? g_cnt[i] : 0;
        int s = v;
        #pragma unroll
        for (int off = 1; off < 32; off <<= 1) {
            int t = __shfl_up_sync(0xffffffffu, s, off);
            if (lane >= off) s += t;
        }
        if (lane == 31) wsum[wd] = s;
        __syncthreads();
        if (wd == 0) {
            int ws = wsum[lane];
            #pragma unroll
            for (int off = 1; off < 32; off <<= 1) {
                int t = __shfl_up_sync(0xffffffffu, ws, off);
                if (lane >= off) ws += t;
            }
            wsum[lane] = ws;
        }
        __syncthreads();
        int wpre = (wd > 0) ? wsum[wd - 1] : 0;
        int incl = s + wpre;
        int base = base_s;
        if (i < N_NODES) {
            g_offs[i] = base + incl - v;
            g_cursor[i] = base + incl - v;
        }
        __syncthreads();
        if (tid == 1023) base_s = base + incl;
        __syncthreads();
    }
    if (tid == 0) g_offs[N_NODES] = N_EDGES;
}
__global__ void fill_kernel(const int* __restrict__ dst) {
    int e = blockIdx.x * blockDim.x + threadIdx.x;
    if (e < N_EDGES) g_csr[atomicAdd(&g_cursor[dst[e]], 1)] = e;
}

// ---------------- prep: weights + input activation split ----------------
__global__ void prep_w_kernel(const float* __restrict__ Wl, const float* __restrict__ Wr,
                              const float* __restrict__ bl, const float* __restrict__ br,
                              const float* __restrict__ Wf) {
    int i = blockIdx.x * blockDim.x + threadIdx.x;
    if (i < 1024 * 128) {
        int n = i >> 7, k = i & 127;
        float v = (n < 512) ? Wl[k * 512 + n] : Wr[k * 512 + (n - 512)];
        __nv_bfloat16 hi, lo;
        split_bf16(v, hi, lo);
        g_wlr[(size_t)n * KK + k] = hi;
        g_wlr[(size_t)n * KK + 128 + k] = lo;
        if (k == 0) g_blr[n] = (n < 512) ? bl[n] : br[n - 512];
    } else if (i < 1024 * 128 + 128 * 128) {
        int j = i - 1024 * 128;
        int n = j >> 7, k = j & 127;
        __nv_bfloat16 hi, lo;
        split_bf16(Wf[k * 128 + n], hi, lo);
        g_wf[(size_t)n * KK + k] = hi;
        g_wf[(size_t)n * KK + 128 + k] = lo;
    }
}
__global__ void split_act_kernel(const float* __restrict__ src) {
    int i = blockIdx.x * blockDim.x + threadIdx.x;
    if (i < N_NODES * 128) {
        int r = i >> 7, c = i & 127;
        __nv_bfloat16 hi, lo;
        split_bf16(src[i], hi, lo);
        g_hh[(size_t)r * KK + c] = hi;
        g_hh[(size_t)r * KK + 128 + c] = lo;
    }
}

// ---------------- bf16 mma.sync GEMM, phased-A, 3 CTAs/SM (round-9, unchanged) ----------------
#define A_LDKB 272
#define A_HALF_BYTES (128 * A_LDKB)
#define B_LDKB 528
#define B_BYTES (64 * B_LDKB)
#define GEMM_SMEM (A_HALF_BYTES + B_BYTES)   // 68608 -> 3 CTAs/SM

__device__ __forceinline__ void ldsm4(uint32_t* r, uint32_t addr) {
    asm volatile("ldmatrix.sync.aligned.m8n8.x4.shared.b16 {%0,%1,%2,%3}, [%4];"
                 : "=r"(r[0]), "=r"(r[1]), "=r"(r[2]), "=r"(r[3]) : "r"(addr));
}
__device__ __forceinline__ void mma16816(float* c, const uint32_t* a, const uint32_t* b) {
    asm volatile(
        "mma.sync.aligned.m16n8k16.row.col.f32.bf16.bf16.f32 "
        "{%0,%1,%2,%3}, {%4,%5,%6,%7}, {%8,%9}, {%0,%1,%2,%3};"
        : "+f"(c[0]), "+f"(c[1]), "+f"(c[2]), "+f"(c[3])
        : "r"(a[0]), "r"(a[1]), "r"(a[2]), "r"(a[3]), "r"(b[0]), "r"(b[1]));
}
__device__ __forceinline__ void loadA(char* smem, int tid, int m0, int kbase, int M) {
    #pragma unroll
    for (int c = tid; c < 2048; c += 256) {
        int r = c >> 4;
        int kc = (c & 15) * 8;
        int gm = m0 + r;
        uint4 v = make_uint4(0, 0, 0, 0);
        if (gm < M) v = *(const uint4*)&g_hh[(size_t)gm * KK + kbase + kc];
        *(uint4*)(smem + r * A_LDKB + kc * 2) = v;
    }
}

template <int DSTSEL>
__global__ void __launch_bounds__(256, 3)
mma_gemm(const float* __restrict__ bias_param, int M) {
    extern __shared__ char smem[];
    uint32_t usb = smem_u32(smem);
    int tid = threadIdx.x, wid = tid >> 5, lane = tid & 31;
    int m0 = blockIdx.y * 128;
    int n0 = blockIdx.x * 64;

    const __nv_bfloat16* Bw = (DSTSEL == 0) ? g_wf : g_wlr;
    const float* bias = (DSTSEL == 0) ? bias_param : g_blr;

    loadA(smem, tid, m0, 0, M);
    #pragma unroll
    for (int c = tid; c < 2048; c += 256) {
        int r = c >> 5;
        int kc = (c & 31) * 8;
        uint4 v = *(const uint4*)&Bw[(size_t)(n0 + r) * KK + kc];
        *(uint4*)(smem + A_HALF_BYTES + r * B_LDKB + kc * 2) = v;
    }
    __syncthreads();

    int wm = wid & 3;
    int wn = wid >> 2;

    uint32_t aoff = usb + (uint32_t)((wm * 32 + (lane & 15)) * A_LDKB + ((lane >> 4) * 8) * 2);
    uint32_t boff = usb + A_HALF_BYTES +
        (uint32_t)((wn * 32 + ((lane >> 4) << 3) + (lane & 7)) * B_LDKB + (((lane >> 3) & 1) * 8) * 2);

    float acc[2][4][4];
    #pragma unroll
    for (int i = 0; i < 2; i++)
        #pragma unroll
        for (int j = 0; j < 4; j++)
            #pragma unroll
            for (int q = 0; q < 4; q++) acc[i][j][q] = 0.f;

    // phase 1: Ahi x Bhi + Ahi x Blo
    #pragma unroll
    for (int k8 = 0; k8 < 8; k8++) {
        int ak = k8 * 16;
        uint32_t ra[2][4];
        ldsm4(ra[0], aoff + ak * 2);
        ldsm4(ra[1], aoff + ak * 2 + 16 * A_LDKB);

        uint32_t rbh[2][4], rbl[2][4];
        #pragma unroll
        for (int g = 0; g < 2; g++) {
            ldsm4(rbh[g], boff + ak * 2 + g * 16 * B_LDKB);
            ldsm4(rbl[g], boff + (128 + ak) * 2 + g * 16 * B_LDKB);
        }
        #pragma unroll
        for (int mi = 0; mi < 2; mi++)
            #pragma unroll
            for (int g = 0; g < 2; g++) {
                mma16816(acc[mi][2 * g],     ra[mi], &rbh[g][0]);
                mma16816(acc[mi][2 * g + 1], ra[mi], &rbh[g][2]);
                mma16816(acc[mi][2 * g],     ra[mi], &rbl[g][0]);
                mma16816(acc[mi][2 * g + 1], ra[mi], &rbl[g][2]);
            }
    }

    __syncthreads();
    loadA(smem, tid, m0, 128, M);
    __syncthreads();

    // phase 2: Alo x Bhi
    #pragma unroll
    for (int k8 = 0; k8 < 8; k8++) {
        int ak = k8 * 16;
        uint32_t ra[2][4];
        ldsm4(ra[0], aoff + ak * 2);
        ldsm4(ra[1], aoff + ak * 2 + 16 * A_LDKB);

        uint32_t rbh[2][4];
        #pragma unroll
        for (int g = 0; g < 2; g++)
            ldsm4(rbh[g], boff + ak * 2 + g * 16 * B_LDKB);

        #pragma unroll
        for (int mi = 0; mi < 2; mi++)
            #pragma unroll
            for (int g = 0; g < 2; g++) {
                mma16816(acc[mi][2 * g],     ra[mi], &rbh[g][0]);
                mma16816(acc[mi][2 * g + 1], ra[mi], &rbh[g][2]);
            }
    }

    int lr = lane >> 2;
    int lc = (lane & 3) * 2;
    #pragma unroll
    for (int mi = 0; mi < 2; mi++) {
        #pragma unroll
        for (int ni = 0; ni < 4; ni++) {
            int gn = n0 + wn * 32 + ni * 8 + lc;
            float bx = bias[gn], by = bias[gn + 1];
            #pragma unroll
            for (int half = 0; half < 2; half++) {
                int gm = m0 + wm * 32 + mi * 16 + lr + half * 8;
                if (gm < M) {
                    float vx = acc[mi][ni][2 * half] + bx;
                    float vy = acc[mi][ni][2 * half + 1] + by;
                    if (DSTSEL == 0) {
                        __nv_bfloat16 hx, lx, hy, ly;
                        split_bf16(vx, hx, lx);
                        split_bf16(vy, hy, ly);
                        __nv_bfloat162 hh2; hh2.x = hx; hh2.y = hy;
                        __nv_bfloat162 ll2; ll2.x = lx; ll2.y = ly;
                        *(__nv_bfloat162*)&g_hh[(size_t)gm * KK + gn] = hh2;
                        *(__nv_bfloat162*)&g_hh[(size_t)gm * KK + 128 + gn] = ll2;
                    } else {
                        float2 v = make_float2(vx, vy);
                        if (gn < 512) *(float2*)&g_xl[(size_t)gm * 512 + gn] = v;
                        else          *(float2*)&g_xr[(size_t)gm * 512 + (gn - 512)] = v;
                    }
                }
            }
        }
    }
}

// ---------------- fused GATv2 edge/aggregate kernel (round-10 version) ----------------
#define ECH 64
template <int LAST>
__global__ void __launch_bounds__(128)
edge_kernel(const int* __restrict__ esrc,
            const float* __restrict__ eattr,
            const float* __restrict__ We,
            const float* __restrict__ att,
            const float* __restrict__ bias_out,
            float* __restrict__ hout) {
    int n = blockIdx.x;
    int h = threadIdx.x >> 5;
    int l = threadIdx.x & 31;

    __shared__ float comb[H][D];
    __shared__ int   s_src[ECH];
    __shared__ float s_ea0[ECH];
    __shared__ float s_ea1[ECH];

    int basec = h * D + 4 * l;
    float4 xr4 = *(const float4*)&g_xr[(size_t)n * HD + basec];
    float4 at4 = *(const float4*)&att[basec];
    float4 we0 = *(const float4*)&We[basec];
    float4 we1 = *(const float4*)&We[HD + basec];

    float4 acc = make_float4(0.f, 0.f, 0.f, 0.f);
    float m = -INFINITY, denom = 0.f;

    int rs = g_offs[n], re = g_offs[n + 1];
    int total = re - rs + 1;                 // +1 virtual self-loop (last)
    float inv = 1.0f / fmaxf((float)(re - rs), 1.0f);

    for (int base = 0; base < total; base += ECH) {
        int cnt = min(ECH, total - base);
        if (threadIdx.x < cnt) {
            int gi = rs + base + threadIdx.x;
            if (gi < re) {
                int e = g_csr[gi];
                s_src[threadIdx.x] = esrc[e];
                s_ea0[threadIdx.x] = eattr[2 * e];
                s_ea1[threadIdx.x] = eattr[2 * e + 1];
            } else {                         // self-loop (mean edge_attr)
                s_src[threadIdx.x] = n;
                s_ea0[threadIdx.x] = g_easum[2 * n] * inv;
                s_ea1[threadIdx.x] = g_easum[2 * n + 1] * inv;
            }
        }
        __syncthreads();

        float4 xln = *(const float4*)&g_xl[(size_t)s_src[0] * HD + basec];
        for (int j = 0; j < cnt; ++j) {
            float4 xlf;
            if (j + 1 < cnt)
                xlf = *(const float4*)&g_xl[(size_t)s_src[j + 1] * HD + basec];
            float ea0 = s_ea0[j], ea1 = s_ea1[j];

            float t0 = xln.x + xr4.x + ea0 * we0.x + ea1 * we1.x;
            float t1 = xln.y + xr4.y + ea0 * we0.y + ea1 * we1.y;
            float t2 = xln.z + xr4.z + ea0 * we0.z + ea1 * we1.z;
            float t3 = xln.w + xr4.w + ea0 * we0.w + ea1 * we1.w;
            t0 = (t0 > 0.f) ? t0 : 0.2f * t0;
            t1 = (t1 > 0.f) ? t1 : 0.2f * t1;
            t2 = (t2 > 0.f) ? t2 : 0.2f * t2;
            t3 = (t3 > 0.f) ? t3 : 0.2f * t3;
            float p = t0 * at4.x + t1 * at4.y + t2 * at4.z + t3 * at4.w;
            #pragma unroll
            for (int off = 16; off > 0; off >>= 1)
                p += __shfl_xor_sync(0xffffffffu, p, off);

            float nm = fmaxf(m, p);
            float r = __expf(m - nm);
            float w = __expf(p - nm);
            acc.x = acc.x * r + w * xln.x;
            acc.y = acc.y * r + w * xln.y;
            acc.z = acc.z * r + w * xln.z;
            acc.w = acc.w * r + w * xln.w;
            denom = denom * r + w;
            m = nm;
            xln = xlf;
        }
        __syncthreads();     // protect smem stage before next chunk overwrites
    }

    float invd = 1.0f / denom;
    comb[h][4 * l + 0] = acc.x * invd;
    comb[h][4 * l + 1] = acc.y * invd;
    comb[h][4 * l + 2] = acc.z * invd;
    comb[h][4 * l + 3] = acc.w * invd;
    __syncthreads();

    int d = threadIdx.x;
    float v = 0.25f * (comb[0][d] + comb[1][d] + comb[2][d] + comb[3][d]) + bias_out[d];
    v = (v > 0.f) ? v : 0.01f * v;
    if (LAST) {
        hout[(size_t)n * D + d] = v;
    } else {
        __nv_bfloat16 hi, lo;
        split_bf16(v, hi, lo);
        g_hh[(size_t)n * KK + d] = hi;
        g_hh[(size_t)n * KK + 128 + d] = lo;
    }
}

// ---------------- launch (forked-stream graph) ----------------
extern "C" void kernel_launch(void* const* d_in, const int* in_sizes, int n_in,
                              void* d_out, int out_size) {
    const float* x        = (const float*)d_in[0];
    const int* eidx       = (const int*)d_in[1];
    const float* eattr    = (const float*)d_in[2];
    const float* Wf       = (const float*)d_in[3];
    const float* bf       = (const float*)d_in[4];
    const float* Wl       = (const float*)d_in[5];
    const float* bl       = (const float*)d_in[6];
    const float* Wr       = (const float*)d_in[7];
    const float* br       = (const float*)d_in[8];
    const float* We       = (const float*)d_in[9];
    const float* att      = (const float*)d_in[10];
    const float* bias_out = (const float*)d_in[11];
    float* h              = (float*)d_out;

    const int* esrc = eidx;
    const int* edst = eidx + N_EDGES;

    static cudaStream_t s1 = nullptr, s2 = nullptr;
    static cudaEvent_t evFork = nullptr, evCsr = nullptr, evPrep = nullptr;
    if (s1 == nullptr) {
        cudaStreamCreateWithFlags(&s1, cudaStreamNonBlocking);
        cudaStreamCreateWithFlags(&s2, cudaStreamNonBlocking);
        cudaEventCreateWithFlags(&evFork, cudaEventDisableTiming);
        cudaEventCreateWithFlags(&evCsr,  cudaEventDisableTiming);
        cudaEventCreateWithFlags(&evPrep, cudaEventDisableTiming);
        cudaFuncSetAttribute(mma_gemm<0>, cudaFuncAttributeMaxDynamicSharedMemorySize, GEMM_SMEM);
        cudaFuncSetAttribute(mma_gemm<3>, cudaFuncAttributeMaxDynamicSharedMemorySize, GEMM_SMEM);
    }

    const int MTILES = (N_NODES + 127) / 128;   // 157

    // fork: s1 = CSR build, s2 = weight prep, default = activation chain
    cudaEventRecord(evFork, 0);
    cudaStreamWaitEvent(s1, evFork, 0);
    cudaStreamWaitEvent(s2, evFork, 0);

    // s1: CSR chain (independent until first edge_kernel)
    init_kernel<<<(N_NODES + 255) / 256, 256, 0, s1>>>();
    count_kernel<<<(N_EDGES + 255) / 256, 256, 0, s1>>>(edst, eattr);
    scan_kernel<<<1, 1024, 0, s1>>>();
    fill_kernel<<<(N_EDGES + 255) / 256, 256, 0, s1>>>(edst);
    cudaEventRecord(evCsr, s1);

    // s2: weight prep (needed by gemms)
    prep_w_kernel<<<(1024 * 128 + 128 * 128 + 255) / 256, 256, 0, s2>>>(Wl, Wr, bl, br, Wf);
    cudaEventRecord(evPrep, s2);

    // default: input split -> gemms
    split_act_kernel<<<(N_NODES * 128 + 255) / 256, 256>>>(x);
    cudaStreamWaitEvent(0, evPrep, 0);
    mma_gemm<0><<<dim3(2, MTILES), 256, GEMM_SMEM>>>(bf, N_NODES);
    mma_gemm<3><<<dim3(16, MTILES), 256, GEMM_SMEM>>>(nullptr, N_NODES);

    // join CSR before first edge aggregation
    cudaStreamWaitEvent(0, evCsr, 0);

    for (int layer = 0; layer < N_LAYERS; ++layer) {
        if (layer > 0)
            mma_gemm<3><<<dim3(16, MTILES), 256, GEMM_SMEM>>>(nullptr, N_NODES);
        if (layer < N_LAYERS - 1)
            edge_kernel<0><<<N_NODES, 128>>>(esrc, eattr, We, att, bias_out, h);
        else
            edge_kernel<1><<<N_NODES, 128>>>(esrc, eattr, We, att, bias_out, h);
    }
}